// round 15
// baseline (speedup 1.0000x reference)
#include <cuda_runtime.h>
#include <cuda_fp16.h>
#include <cuda.h>
#include <cstdint>
#include <math.h>

#define NROWS 4096
#define DIM   2048
#define NK    4
#define EPSF  1e-6f

// GEMM tiling (fp16, mma.m16n8k16), block 128x256, warp 64x64, 8 warps
#define MT 128
#define NT 256
#define KC 64                     // K halves per stage (128B rows -> SW128)
#define NSTAGE 4
#define NITER (DIM / KC)          // 32
#define A_STAGE_BYTES (MT * 128)               // 16384
#define B_STAGE_BYTES (NT * 128)               // 32768
#define STAGE_BYTES   (A_STAGE_BYTES + B_STAGE_BYTES)   // 49152
#define SOFF_FULL     (NSTAGE * STAGE_BYTES)   // 196608
#define SOFF_EMPTY    (SOFF_FULL + NSTAGE * 8)
#define SMEM_TOTAL    (SOFF_EMPTY + NSTAGE * 8 + 32)

#define NPART 32                  // per-row partial slots (8 n-blocks * 4 n-warps)

#define SCALE     32.0f
#define SCALE_INV 9.765625e-4f    // 1/1024

// k_prep block roles
#define PREP_ROW_BLOCKS 1024      // 4 rows per block
#define PREP_W_BLOCKS   512       // 2048 float4 per block
#define PREP_TOTAL      (PREP_ROW_BLOCKS + PREP_W_BLOCKS + 1)

// ------------------------------------------------------------------
// Device scratch
// ------------------------------------------------------------------
__device__ __half g_hh[(size_t)NROWS * DIM];   // h in fp16 (combine stream)
__device__ __half g_xh[(size_t)NROWS * DIM];
__device__ __half g_wh[(size_t)DIM * DIM];
__device__ float  g_part[(size_t)NROWS * NPART * 5];
__device__ float  g_xn2[NROWS];
__device__ float  g_sp[NROWS];
__device__ float  g_c;
__device__ float  g_sc;
__device__ float  g_an2[NK];
__device__ float  g_w[NK];
__device__ unsigned g_cnt;

// ------------------------------------------------------------------
// Helpers
// ------------------------------------------------------------------
__device__ __forceinline__ uint32_t smem_u32(const void* p) {
    uint32_t a;
    asm("{ .reg .u64 t; cvta.to.shared.u64 t, %1; cvt.u32.u64 %0, t; }"
        : "=r"(a) : "l"(p));
    return a;
}

__device__ __forceinline__ float blockReduceSum(float v, float* sbuf) {
    #pragma unroll
    for (int o = 16; o > 0; o >>= 1) v += __shfl_xor_sync(0xffffffffu, v, o);
    int w = threadIdx.x >> 5;
    if ((threadIdx.x & 31) == 0) sbuf[w] = v;
    __syncthreads();
    if (threadIdx.x < 32) {
        float t = (threadIdx.x < 8) ? sbuf[threadIdx.x] : 0.f;
        #pragma unroll
        for (int o = 4; o > 0; o >>= 1) t += __shfl_xor_sync(0xffffffffu, t, o);
        if (threadIdx.x == 0) sbuf[0] = t;
    }
    __syncthreads();
    float r = sbuf[0];
    __syncthreads();
    return r;
}

__device__ __forceinline__ float clip_artanh_arg(float z) {
    return fminf(fmaxf(z, -1.f + 1e-5f), 1.f - 1e-5f);
}

// Pack 8 scaled floats (two float4) into 8 fp16 in one uint4 (STG.128)
__device__ __forceinline__ uint4 pack8h(float4 a, float4 b) {
    uint4 u;
    __half2* h = (__half2*)&u;
    h[0] = __floats2half2_rn(a.x * SCALE, a.y * SCALE);
    h[1] = __floats2half2_rn(a.z * SCALE, a.w * SCALE);
    h[2] = __floats2half2_rn(b.x * SCALE, b.y * SCALE);
    h[3] = __floats2half2_rn(b.z * SCALE, b.w * SCALE);
    return u;
}

__device__ __forceinline__ void ldsm4(uint32_t addr, uint32_t& r0, uint32_t& r1,
                                      uint32_t& r2, uint32_t& r3) {
    asm volatile("ldmatrix.sync.aligned.m8n8.x4.shared.b16 {%0,%1,%2,%3}, [%4];"
                 : "=r"(r0), "=r"(r1), "=r"(r2), "=r"(r3) : "r"(addr));
}

__device__ __forceinline__ void mbar_init(uint32_t a, uint32_t cnt) {
    asm volatile("mbarrier.init.shared.b64 [%0], %1;" :: "r"(a), "r"(cnt) : "memory");
}

__device__ __forceinline__ void mbar_expect(uint32_t a, uint32_t bytes) {
    asm volatile("mbarrier.arrive.expect_tx.shared.b64 _, [%0], %1;"
                 :: "r"(a), "r"(bytes) : "memory");
}

__device__ __forceinline__ void mbar_arrive(uint32_t a) {
    asm volatile("mbarrier.arrive.release.cta.shared.b64 _, [%0];"
                 :: "r"(a) : "memory");
}

__device__ __forceinline__ void mbar_wait(uint32_t a, uint32_t parity) {
    asm volatile(
        "{\n\t"
        ".reg .pred P;\n\t"
        "W%=:\n\t"
        "mbarrier.try_wait.parity.acquire.cta.shared::cta.b64 P, [%0], %1;\n\t"
        "@P bra D%=;\n\t"
        "bra W%=;\n\t"
        "D%=:\n\t"
        "}"
        :: "r"(a), "r"(parity) : "memory");
}

__device__ __forceinline__ void tma2d(uint32_t dst, const CUtensorMap* map,
                                      int cx, int cy, uint32_t mbar) {
    asm volatile(
        "cp.async.bulk.tensor.2d.shared::cta.global.tile.mbarrier::complete_tx::bytes "
        "[%0], [%1, {%2, %3}], [%4];"
        :: "r"(dst), "l"(map), "r"(cx), "r"(cy), "r"(mbar) : "memory");
}

// ------------------------------------------------------------------
// Kernel 1: fused prep (vectorized 16B fp16 stores).
//   blocks [0,1024): 4 rows each: |x|^2, softplus(x.cw+cb), fp16 (x*32) copy
//   blocks [1024,1536): W -> fp16 (w*32), 2048 float4 per block
//   block 1536: waits for rowstat completion, computes scalars, resets counter
// ------------------------------------------------------------------
__global__ __launch_bounds__(256) void k_prep(const float* __restrict__ x,
                                              const float* __restrict__ cw,
                                              const float* __restrict__ cb,
                                              const float* __restrict__ W,
                                              const float* __restrict__ anchors,
                                              const float* __restrict__ aw) {
    int bid = blockIdx.x;
    int tid = threadIdx.x;

    if (bid < PREP_ROW_BLOCKS) {
        // ---- rowstat: rows r0..r0+3; thread owns 8 consecutive floats ----
        int r0 = bid * 4;
        const float4* cr = (const float4*)cw;
        float4 c0 = cr[tid * 2];
        float4 c1 = cr[tid * 2 + 1];
        float v[8];
        #pragma unroll
        for (int r = 0; r < 4; r++) {
            const float4* xr = (const float4*)(x + (size_t)(r0 + r) * DIM);
            float4 a0 = xr[tid * 2];
            float4 a1 = xr[tid * 2 + 1];
            v[r] = a0.x * c0.x + a0.y * c0.y + a0.z * c0.z + a0.w * c0.w
                 + a1.x * c1.x + a1.y * c1.y + a1.z * c1.z + a1.w * c1.w;
            v[4 + r] = a0.x * a0.x + a0.y * a0.y + a0.z * a0.z + a0.w * a0.w
                     + a1.x * a1.x + a1.y * a1.y + a1.z * a1.z + a1.w * a1.w;
            ((uint4*)(g_xh + (size_t)(r0 + r) * DIM))[tid] = pack8h(a0, a1);
        }
        // 8-quantity reduce: warp shfl then 8x8 cross-warp
        __shared__ float sbuf[8 * 8];
        #pragma unroll
        for (int q = 0; q < 8; q++) {
            #pragma unroll
            for (int o = 16; o > 0; o >>= 1)
                v[q] += __shfl_xor_sync(0xffffffffu, v[q], o);
        }
        int w = tid >> 5;
        if ((tid & 31) == 0) {
            #pragma unroll
            for (int q = 0; q < 8; q++) sbuf[w * 8 + q] = v[q];
        }
        __syncthreads();
        if (tid < 64) {
            int q = tid >> 3, ww = tid & 7;
            float t = sbuf[ww * 8 + q];
            t += __shfl_xor_sync(0xffffffffu, t, 1);
            t += __shfl_xor_sync(0xffffffffu, t, 2);
            t += __shfl_xor_sync(0xffffffffu, t, 4);
            if (ww == 0) {
                if (q < 4) {
                    float l = t + cb[0];
                    g_sp[r0 + q] = fmaxf(l, 0.f) + log1pf(expf(-fabsf(l)));
                } else {
                    g_xn2[r0 + q - 4] = t;
                }
            }
        }
        __syncthreads();
        if (tid == 0) {
            __threadfence();
            atomicAdd(&g_cnt, 1u);
        }
    } else if (bid < PREP_ROW_BLOCKS + PREP_W_BLOCKS) {
        // ---- W convert: thread owns 32 consecutive floats (4 x uint4 out) ----
        int b = bid - PREP_ROW_BLOCKS;
        const float4* Wf = (const float4*)W + (size_t)b * 2048 + tid * 8;
        uint4* o = (uint4*)g_wh + (size_t)b * 1024 + tid * 4;
        float4 vv[8];
        #pragma unroll
        for (int j = 0; j < 8; j++) vv[j] = Wf[j];
        #pragma unroll
        for (int j = 0; j < 4; j++) o[j] = pack8h(vv[2 * j], vv[2 * j + 1]);
    } else {
        // ---- scalars: wait for all rowstat blocks ----
        if (tid == 0) {
            while (((volatile unsigned*)&g_cnt)[0] < (unsigned)PREP_ROW_BLOCKS)
                __nanosleep(128);
        }
        __syncthreads();
        __threadfence();

        __shared__ float sbuf[8];
        float s = 0.f;
        for (int i = tid; i < NROWS; i += 256) s += g_sp[i];
        s = blockReduceSum(s, sbuf);
        float c = s / (float)NROWS;

        for (int k = 0; k < NK; k++) {
            float v = 0.f;
            for (int j = tid; j < DIM; j += 256) {
                float a = anchors[k * DIM + j];
                v += a * a;
            }
            v = blockReduceSum(v, sbuf);
            if (tid == 0) g_an2[k] = v;
        }

        if (tid == 0) {
            g_c = c;
            g_sc = sqrtf(c);
            float m = fmaxf(fmaxf(aw[0], aw[1]), fmaxf(aw[2], aw[3]));
            float e0 = expf(aw[0] - m), e1 = expf(aw[1] - m);
            float e2 = expf(aw[2] - m), e3 = expf(aw[3] - m);
            float inv = 1.f / (e0 + e1 + e2 + e3);
            g_w[0] = e0 * inv; g_w[1] = e1 * inv;
            g_w[2] = e2 * inv; g_w[3] = e3 * inv;
            g_cnt = 0;          // reset for next graph replay
            __threadfence();
        }
    }
}

// ------------------------------------------------------------------
// Kernel 2: TMA-fed fp16 mma.sync GEMM, mbarrier-only mainloop
// ------------------------------------------------------------------
__device__ __forceinline__ float row_scale(int r, float sc) {
    float n = fmaxf(sqrtf(g_xn2[r]), EPSF);
    float z = sc * n;
    return atanhf(clip_artanh_arg(z)) / z;
}

__global__ void __launch_bounds__(256, 1) k_gemm(
    const __grid_constant__ CUtensorMap xmap,
    const __grid_constant__ CUtensorMap wmap,
    const float* __restrict__ bias,
    const float* __restrict__ anchors)
{
    extern __shared__ char smem[];
    uint32_t sb = smem_u32(smem);
    const int tid  = threadIdx.x;
    const int lane = tid & 31;
    const int warp = tid >> 5;
    const int bm = blockIdx.y * MT;
    const int bn = blockIdx.x * NT;
    const int wm = (warp >> 2) * 64;   // 2 M-warps
    const int wn = (warp & 3) * 64;    // 4 N-warps
    const uint32_t mbF = sb + SOFF_FULL;
    const uint32_t mbE = sb + SOFF_EMPTY;

    float acc[4][8][4];
    #pragma unroll
    for (int mi = 0; mi < 4; mi++)
        #pragma unroll
        for (int ni = 0; ni < 8; ni++)
            #pragma unroll
            for (int q = 0; q < 4; q++) acc[mi][ni][q] = 0.f;

    const int g  = lane >> 2;
    const int tg = lane & 3;

    // ldmatrix per-lane addressing (SW128 swizzle: row*128 + (kb ^ ((row&7)<<4)))
    const uint32_t a_row = wm + (lane & 15);
    const uint32_t aq    = ((lane >> 4) * 16) ^ ((a_row & 7) << 4);
    const uint32_t b_row = wn + ((lane >> 4) << 3) + (lane & 7);
    const uint32_t bq    = (((lane >> 3) & 1) * 16) ^ ((b_row & 7) << 4);

    if (tid == 0) {
        #pragma unroll
        for (int s = 0; s < NSTAGE; s++) {
            mbar_init(mbF + 8 * s, 1);
            mbar_init(mbE + 8 * s, 8);   // one arrive per warp
        }
    }
    __syncthreads();
    if (tid == 0) {
        #pragma unroll
        for (int s = 0; s < 3; s++) {
            uint32_t abase = sb + s * STAGE_BYTES;
            mbar_expect(mbF + 8 * s, STAGE_BYTES);
            tma2d(abase, &xmap, s * KC, bm, mbF + 8 * s);
            tma2d(abase + A_STAGE_BYTES, &wmap, s * KC, bn, mbF + 8 * s);
        }
    }

    for (int i = 0; i < NITER; i++) {
        int s = i & 3;
        mbar_wait(mbF + 8 * s, (i >> 2) & 1);
        uint32_t abase = sb + s * STAGE_BYTES;
        uint32_t bbase = abase + A_STAGE_BYTES;

        #pragma unroll
        for (int ks = 0; ks < 4; ks++) {
            uint32_t a[4][4];
            #pragma unroll
            for (int mi = 0; mi < 4; mi++)
                ldsm4(abase + (a_row + mi * 16) * 128 + ((ks * 32) ^ aq),
                      a[mi][0], a[mi][1], a[mi][2], a[mi][3]);
            uint32_t b[8][2];
            #pragma unroll
            for (int p = 0; p < 4; p++)
                ldsm4(bbase + (b_row + p * 16) * 128 + ((ks * 32) ^ bq),
                      b[2 * p][0], b[2 * p][1], b[2 * p + 1][0], b[2 * p + 1][1]);
            #pragma unroll
            for (int mi = 0; mi < 4; mi++)
                #pragma unroll
                for (int ni = 0; ni < 8; ni++) {
                    asm volatile(
                        "mma.sync.aligned.m16n8k16.row.col.f32.f16.f16.f32 "
                        "{%0,%1,%2,%3}, {%4,%5,%6,%7}, {%8,%9}, {%0,%1,%2,%3};\n"
                        : "+f"(acc[mi][ni][0]), "+f"(acc[mi][ni][1]),
                          "+f"(acc[mi][ni][2]), "+f"(acc[mi][ni][3])
                        : "r"(a[mi][0]), "r"(a[mi][1]), "r"(a[mi][2]), "r"(a[mi][3]),
                          "r"(b[ni][0]), "r"(b[ni][1]));
                }
        }
        // Fragments for stage s fully consumed by this warp -> release buffer.
        if (lane == 0) mbar_arrive(mbE + 8 * s);

        // Producer: refill stage (i+3)&3 once all warps released it (iter i-1).
        if (tid == 0 && i + 3 < NITER) {
            int j = i + 3, s2 = j & 3, f = j >> 2;
            if (f >= 1) mbar_wait(mbE + 8 * s2, (f - 1) & 1);
            uint32_t ab2 = sb + s2 * STAGE_BYTES;
            mbar_expect(mbF + 8 * s2, STAGE_BYTES);
            tma2d(ab2, &xmap, j * KC, bm, mbF + 8 * s2);
            tma2d(ab2 + A_STAGE_BYTES, &wmap, j * KC, bn, mbF + 8 * s2);
        }
    }

    // Epilogue: h = s_row * acc/1024 + bias; fp16 store + per-row partials
    float sc = g_sc;
    float bz0[8], bz1[8];
    #pragma unroll
    for (int ni = 0; ni < 8; ni++) {
        int cc = bn + wn + ni * 8 + tg * 2;
        bz0[ni] = bias[cc];
        bz1[ni] = bias[cc + 1];
    }
    #pragma unroll
    for (int mi = 0; mi < 4; mi++) {
        int r0 = bm + wm + mi * 16 + g;
        float s0 = row_scale(r0, sc) * SCALE_INV;
        float s1 = row_scale(r0 + 8, sc) * SCALE_INV;
        float p0[5] = {0.f, 0.f, 0.f, 0.f, 0.f};
        float p1[5] = {0.f, 0.f, 0.f, 0.f, 0.f};
        #pragma unroll
        for (int ni = 0; ni < 8; ni++) {
            int cc = bn + wn + ni * 8 + tg * 2;
            float h00 = fmaf(s0, acc[mi][ni][0], bz0[ni]);
            float h01 = fmaf(s0, acc[mi][ni][1], bz1[ni]);
            float h10 = fmaf(s1, acc[mi][ni][2], bz0[ni]);
            float h11 = fmaf(s1, acc[mi][ni][3], bz1[ni]);
            *(__half2*)(g_hh + (size_t)r0 * DIM + cc) = __floats2half2_rn(h00, h01);
            *(__half2*)(g_hh + (size_t)(r0 + 8) * DIM + cc) = __floats2half2_rn(h10, h11);
            p0[0] += h00 * h00 + h01 * h01;
            p1[0] += h10 * h10 + h11 * h11;
            #pragma unroll
            for (int k = 0; k < NK; k++) {
                float a0 = anchors[k * DIM + cc];
                float a1 = anchors[k * DIM + cc + 1];
                p0[1 + k] += h00 * a0 + h01 * a1;
                p1[1 + k] += h10 * a0 + h11 * a1;
            }
        }
        #pragma unroll
        for (int q = 0; q < 5; q++) {
            p0[q] += __shfl_xor_sync(0xffffffffu, p0[q], 1);
            p0[q] += __shfl_xor_sync(0xffffffffu, p0[q], 2);
            p1[q] += __shfl_xor_sync(0xffffffffu, p1[q], 1);
            p1[q] += __shfl_xor_sync(0xffffffffu, p1[q], 2);
        }
        if (tg == 0) {
            int pi = blockIdx.x * 4 + (warp & 3);   // 8 n-blocks * 4 n-warps = 32
            float* d0 = g_part + ((size_t)r0 * NPART + pi) * 5;
            float* d1 = g_part + ((size_t)(r0 + 8) * NPART + pi) * 5;
            #pragma unroll
            for (int q = 0; q < 5; q++) { d0[q] = p0[q]; d1[q] = p1[q]; }
        }
    }
}

// ------------------------------------------------------------------
// Kernel 3: per-row coefficients + streaming combine (h from fp16)
// ------------------------------------------------------------------
__global__ __launch_bounds__(256) void k_final(const float* __restrict__ anchors,
                                               const float* __restrict__ tv,
                                               float* __restrict__ out) {
    int row = blockIdx.x;
    int tid = threadIdx.x;
    int w = tid >> 5, lane = tid & 31;

    __shared__ float sred[5];
    __shared__ float scoef[5];

    // Reduce 32 partials x 5 quantities: warp q handles quantity q
    if (w < 5) {
        const float* pp = g_part + (size_t)row * NPART * 5;
        float v = pp[lane * 5 + w];
        #pragma unroll
        for (int o = 16; o > 0; o >>= 1) v += __shfl_xor_sync(0xffffffffu, v, o);
        if (lane == 0) sred[w] = v;
    }
    __syncthreads();

    if (tid == 0) {
        float c = g_c, sc = g_sc;
        float h2 = sred[0];
        float m = fmaxf(sqrtf(h2), EPSF);
        float scm = sc * m;
        float e = tanhf(scm) / scm;
        float y2 = e * e * h2;
        float Acoef = 0.f;
        #pragma unroll
        for (int k = 0; k < NK; k++) {
            float ya  = e * sred[1 + k];
            float an2 = g_an2[k];
            float P  = 1.f - 2.f * c * ya + c * an2;
            float Q  = 1.f - c * y2;
            float D1 = fmaxf(1.f - 2.f * c * ya + c * c * y2 * an2, EPSF);
            float diff2 = (P * P * y2 - 2.f * P * Q * ya + Q * Q * an2) / (D1 * D1);
            float nd = fmaxf(sqrtf(fmaxf(diff2, 0.f)), EPSF);
            float z  = sc * nd;
            float ar = atanhf(clip_artanh_arg(z));
            float tau = tanhf(tv[k] * ar) / z;
            float uy = -tau * P / D1;
            float ua =  tau * Q / D1;
            float xys = uy * y2 + ua * ya;
            float y2s = tau * tau * diff2;
            float den2 = fmaxf(1.f + 2.f * c * xys + c * c * y2 * y2s, EPSF);
            float alpha = (1.f + 2.f * c * xys + c * y2s + (1.f - c * y2) * uy) / den2;
            float beta  = (1.f - c * y2) * ua / den2;
            float w2 = g_w[k];
            Acoef += w2 * alpha;
            scoef[1 + k] = w2 * beta;
        }
        scoef[0] = Acoef * e;
    }
    __syncthreads();

    float Ae = scoef[0];
    float B0 = scoef[1], B1 = scoef[2], B2 = scoef[3], B3 = scoef[4];
    const __half2* hr = (const __half2*)(g_hh + (size_t)row * DIM);
    const float4* a0 = (const float4*)(anchors);
    const float4* a1 = (const float4*)(anchors + DIM);
    const float4* a2 = (const float4*)(anchors + 2 * DIM);
    const float4* a3 = (const float4*)(anchors + 3 * DIM);
    float4* outr = (float4*)(out + (size_t)row * DIM);
    #pragma unroll
    for (int i = 0; i < 2; i++) {
        int idx = tid + i * 256;
        float2 hlo = __half22float2(hr[idx * 2]);
        float2 hhi = __half22float2(hr[idx * 2 + 1]);
        float4 v0 = a0[idx], v1 = a1[idx], v2 = a2[idx], v3 = a3[idx];
        float4 o;
        o.x = Ae * hlo.x; o.y = Ae * hlo.y; o.z = Ae * hhi.x; o.w = Ae * hhi.y;
        o.x = fmaf(B0, v0.x, o.x); o.y = fmaf(B0, v0.y, o.y);
        o.z = fmaf(B0, v0.z, o.z); o.w = fmaf(B0, v0.w, o.w);
        o.x = fmaf(B1, v1.x, o.x); o.y = fmaf(B1, v1.y, o.y);
        o.z = fmaf(B1, v1.z, o.z); o.w = fmaf(B1, v1.w, o.w);
        o.x = fmaf(B2, v2.x, o.x); o.y = fmaf(B2, v2.y, o.y);
        o.z = fmaf(B2, v2.z, o.z); o.w = fmaf(B2, v2.w, o.w);
        o.x = fmaf(B3, v3.x, o.x); o.y = fmaf(B3, v3.y, o.y);
        o.z = fmaf(B3, v3.z, o.z); o.w = fmaf(B3, v3.w, o.w);
        outr[idx] = o;
    }
}

// ------------------------------------------------------------------
// Launch
// ------------------------------------------------------------------
typedef CUresult (*tmapEncodeFn)(
    CUtensorMap*, CUtensorMapDataType, cuuint32_t, void*,
    const cuuint64_t*, const cuuint64_t*, const cuuint32_t*, const cuuint32_t*,
    CUtensorMapInterleave, CUtensorMapSwizzle, CUtensorMapL2promotion,
    CUtensorMapFloatOOBfill);

extern "C" void kernel_launch(void* const* d_in, const int* in_sizes, int n_in,
                              void* d_out, int out_size) {
    const float* x       = (const float*)d_in[0];
    const float* weight  = (const float*)d_in[1];
    const float* bias    = (const float*)d_in[2];
    const float* cw      = (const float*)d_in[3];
    const float* cb      = (const float*)d_in[4];
    const float* anchors = (const float*)d_in[5];
    const float* tv      = (const float*)d_in[6];
    const float* aw      = (const float*)d_in[7];
    float* out = (float*)d_out;

    cudaFuncSetAttribute(k_gemm, cudaFuncAttributeMaxDynamicSharedMemorySize,
                         SMEM_TOTAL);

    // Build tensor maps for the fp16 scratch tensors
    void* xptr = nullptr;
    void* wptr = nullptr;
    cudaGetSymbolAddress(&xptr, g_xh);
    cudaGetSymbolAddress(&wptr, g_wh);

    tmapEncodeFn encode = nullptr;
    cudaDriverEntryPointQueryResult qr;
    cudaGetDriverEntryPointByVersion("cuTensorMapEncodeTiled", (void**)&encode,
                                     12000, cudaEnableDefault, &qr);

    CUtensorMap xmap, wmap;
    {
        cuuint64_t gdim[2] = {DIM, NROWS};
        cuuint64_t gstr[1] = {DIM * 2};           // bytes between rows
        cuuint32_t box[2]  = {KC, MT};            // 64 halves x 128 rows
        cuuint32_t est[2]  = {1, 1};
        encode(&xmap, CU_TENSOR_MAP_DATA_TYPE_UINT16, 2, xptr,
               gdim, gstr, box, est,
               CU_TENSOR_MAP_INTERLEAVE_NONE, CU_TENSOR_MAP_SWIZZLE_128B,
               CU_TENSOR_MAP_L2_PROMOTION_L2_128B,
               CU_TENSOR_MAP_FLOAT_OOB_FILL_NONE);
    }
    {
        cuuint64_t gdim[2] = {DIM, DIM};
        cuuint64_t gstr[1] = {DIM * 2};
        cuuint32_t box[2]  = {KC, NT};            // 64 halves x 256 rows
        cuuint32_t est[2]  = {1, 1};
        encode(&wmap, CU_TENSOR_MAP_DATA_TYPE_UINT16, 2, wptr,
               gdim, gstr, box, est,
               CU_TENSOR_MAP_INTERLEAVE_NONE, CU_TENSOR_MAP_SWIZZLE_128B,
               CU_TENSOR_MAP_L2_PROMOTION_L2_128B,
               CU_TENSOR_MAP_FLOAT_OOB_FILL_NONE);
    }

    k_prep<<<PREP_TOTAL, 256>>>(x, cw, cb, weight, anchors, aw);
    dim3 grid(DIM / NT, NROWS / MT);       // 8 x 32 = 256 CTAs
    k_gemm<<<grid, 256, SMEM_TOTAL>>>(xmap, wmap, bias, anchors);
    k_final<<<NROWS, 256>>>(anchors, tv, out);
}

// round 17
// speedup vs baseline: 1.0872x; 1.0872x over previous
#include <cuda_runtime.h>
#include <cuda_fp16.h>
#include <cuda.h>
#include <cstdint>
#include <math.h>

#define NROWS 4096
#define DIM   2048
#define NK    4
#define EPSF  1e-6f

// GEMM tiling (fp16, mma.m16n8k16), block 128x256, warp 64x64, 8 warps
#define MT 128
#define NT 256
#define KC 64                     // K halves per stage (128B rows -> SW128)
#define NSTAGE 4
#define NITER (DIM / KC)          // 32
#define A_STAGE_BYTES (MT * 128)               // 16384
#define B_STAGE_BYTES (NT * 128)               // 32768
#define STAGE_BYTES   (A_STAGE_BYTES + B_STAGE_BYTES)   // 49152
#define SOFF_FULL     (NSTAGE * STAGE_BYTES)   // 196608
#define SOFF_EMPTY    (SOFF_FULL + NSTAGE * 8)
#define SOFF_SCRATCH  (SOFF_EMPTY + NSTAGE * 8)          // 32B reduce scratch
#define SMEM_TOTAL    (SOFF_SCRATCH + 64)

#define NPART 32                  // per-row partial slots (8 n-blocks * 4 n-warps)

#define SCALE     32.0f
#define SCALE_INV 9.765625e-4f    // 1/1024

// k_prep block roles
#define PREP_ROW_BLOCKS 1024      // 4 rows per block
#define PREP_W_BLOCKS   512       // 2048 float4 per block
#define PREP_TOTAL      (PREP_ROW_BLOCKS + PREP_W_BLOCKS)

// ------------------------------------------------------------------
// Device scratch
// ------------------------------------------------------------------
__device__ __half g_hh[(size_t)NROWS * DIM];   // h in fp16 (combine stream)
__device__ __half g_xh[(size_t)NROWS * DIM];
__device__ __half g_wh[(size_t)DIM * DIM];
__device__ float  g_part[(size_t)NROWS * NPART * 5];
__device__ float  g_xn2[NROWS];
__device__ float  g_sp[NROWS];
__device__ float  g_c;
__device__ float  g_sc;
__device__ float  g_an2[NK];
__device__ float  g_w[NK];
__device__ unsigned g_sflag;      // scalars-ready flag (reset by k_final)

// ------------------------------------------------------------------
// Helpers
// ------------------------------------------------------------------
__device__ __forceinline__ uint32_t smem_u32(const void* p) {
    uint32_t a;
    asm("{ .reg .u64 t; cvta.to.shared.u64 t, %1; cvt.u32.u64 %0, t; }"
        : "=r"(a) : "l"(p));
    return a;
}

__device__ __forceinline__ float blockReduceSum(float v, float* sbuf) {
    #pragma unroll
    for (int o = 16; o > 0; o >>= 1) v += __shfl_xor_sync(0xffffffffu, v, o);
    int w = threadIdx.x >> 5;
    if ((threadIdx.x & 31) == 0) sbuf[w] = v;
    __syncthreads();
    if (threadIdx.x < 32) {
        float t = (threadIdx.x < 8) ? sbuf[threadIdx.x] : 0.f;
        #pragma unroll
        for (int o = 4; o > 0; o >>= 1) t += __shfl_xor_sync(0xffffffffu, t, o);
        if (threadIdx.x == 0) sbuf[0] = t;
    }
    __syncthreads();
    float r = sbuf[0];
    __syncthreads();
    return r;
}

__device__ __forceinline__ float clip_artanh_arg(float z) {
    return fminf(fmaxf(z, -1.f + 1e-5f), 1.f - 1e-5f);
}

__device__ __forceinline__ void ldsm4(uint32_t addr, uint32_t& r0, uint32_t& r1,
                                      uint32_t& r2, uint32_t& r3) {
    asm volatile("ldmatrix.sync.aligned.m8n8.x4.shared.b16 {%0,%1,%2,%3}, [%4];"
                 : "=r"(r0), "=r"(r1), "=r"(r2), "=r"(r3) : "r"(addr));
}

__device__ __forceinline__ void mbar_init(uint32_t a, uint32_t cnt) {
    asm volatile("mbarrier.init.shared.b64 [%0], %1;" :: "r"(a), "r"(cnt) : "memory");
}

__device__ __forceinline__ void mbar_expect(uint32_t a, uint32_t bytes) {
    asm volatile("mbarrier.arrive.expect_tx.shared.b64 _, [%0], %1;"
                 :: "r"(a), "r"(bytes) : "memory");
}

__device__ __forceinline__ void mbar_arrive(uint32_t a) {
    asm volatile("mbarrier.arrive.release.cta.shared.b64 _, [%0];"
                 :: "r"(a) : "memory");
}

__device__ __forceinline__ void mbar_wait(uint32_t a, uint32_t parity) {
    asm volatile(
        "{\n\t"
        ".reg .pred P;\n\t"
        "W%=:\n\t"
        "mbarrier.try_wait.parity.acquire.cta.shared::cta.b64 P, [%0], %1;\n\t"
        "@P bra D%=;\n\t"
        "bra W%=;\n\t"
        "D%=:\n\t"
        "}"
        :: "r"(a), "r"(parity) : "memory");
}

__device__ __forceinline__ void tma2d(uint32_t dst, const CUtensorMap* map,
                                      int cx, int cy, uint32_t mbar) {
    asm volatile(
        "cp.async.bulk.tensor.2d.shared::cta.global.tile.mbarrier::complete_tx::bytes "
        "[%0], [%1, {%2, %3}], [%4];"
        :: "r"(dst), "l"(map), "r"(cx), "r"(cy), "r"(mbar) : "memory");
}

// ------------------------------------------------------------------
// Kernel 1: fused prep (pure streaming; no atomics, no tail block).
//   blocks [0,1024): 4 rows each: |x|^2, softplus(x.cw+cb), fp16 (x*32) copy
//   blocks [1024,1536): W -> fp16 (w*32), 2048 float4 per block
// ------------------------------------------------------------------
__global__ __launch_bounds__(256) void k_prep(const float* __restrict__ x,
                                              const float* __restrict__ cw,
                                              const float* __restrict__ cb,
                                              const float* __restrict__ W) {
    int bid = blockIdx.x;
    int tid = threadIdx.x;

    if (bid < PREP_ROW_BLOCKS) {
        // ---- rowstat: rows r0..r0+3 ----
        int r0 = bid * 4;
        const float4* cr = (const float4*)cw;
        float4 c0 = cr[tid];
        float4 c1 = cr[tid + 256];
        float4 a[4][2];
        #pragma unroll
        for (int r = 0; r < 4; r++) {
            const float4* xr = (const float4*)(x + (size_t)(r0 + r) * DIM);
            a[r][0] = xr[tid];
            a[r][1] = xr[tid + 256];
        }
        float v[8];
        #pragma unroll
        for (int r = 0; r < 4; r++) {
            float4 a0 = a[r][0], a1 = a[r][1];
            v[r] = a0.x * c0.x + a0.y * c0.y + a0.z * c0.z + a0.w * c0.w
                 + a1.x * c1.x + a1.y * c1.y + a1.z * c1.z + a1.w * c1.w;
            v[4 + r] = a0.x * a0.x + a0.y * a0.y + a0.z * a0.z + a0.w * a0.w
                     + a1.x * a1.x + a1.y * a1.y + a1.z * a1.z + a1.w * a1.w;
            __half2* xo = (__half2*)(g_xh + (size_t)(r0 + r) * DIM);
            xo[tid * 2]     = __floats2half2_rn(a0.x * SCALE, a0.y * SCALE);
            xo[tid * 2 + 1] = __floats2half2_rn(a0.z * SCALE, a0.w * SCALE);
            xo[(tid + 256) * 2]     = __floats2half2_rn(a1.x * SCALE, a1.y * SCALE);
            xo[(tid + 256) * 2 + 1] = __floats2half2_rn(a1.z * SCALE, a1.w * SCALE);
        }
        // 8-quantity reduce: warp shfl then 8x8 cross-warp
        __shared__ float sbuf[8 * 8];
        #pragma unroll
        for (int q = 0; q < 8; q++) {
            #pragma unroll
            for (int o = 16; o > 0; o >>= 1)
                v[q] += __shfl_xor_sync(0xffffffffu, v[q], o);
        }
        int w = tid >> 5;
        if ((tid & 31) == 0) {
            #pragma unroll
            for (int q = 0; q < 8; q++) sbuf[w * 8 + q] = v[q];
        }
        __syncthreads();
        if (tid < 64) {
            int q = tid >> 3, ww = tid & 7;
            float t = sbuf[ww * 8 + q];
            t += __shfl_xor_sync(0xffffffffu, t, 1);
            t += __shfl_xor_sync(0xffffffffu, t, 2);
            t += __shfl_xor_sync(0xffffffffu, t, 4);
            if (ww == 0) {
                if (q < 4) {
                    float l = t + cb[0];
                    g_sp[r0 + q] = fmaxf(l, 0.f) + log1pf(expf(-fabsf(l)));
                } else {
                    g_xn2[r0 + q - 4] = t;
                }
            }
        }
    } else {
        // ---- W convert: 512 blocks x 256 thr x 8 float4 ----
        int b = bid - PREP_ROW_BLOCKS;
        __half2* o = (__half2*)g_wh;
        float4 vv[8];
        #pragma unroll
        for (int j = 0; j < 8; j++)
            vv[j] = ((const float4*)W)[b * 2048 + j * 256 + tid];
        #pragma unroll
        for (int j = 0; j < 8; j++) {
            int i = b * 2048 + j * 256 + tid;
            o[i * 2]     = __floats2half2_rn(vv[j].x * SCALE, vv[j].y * SCALE);
            o[i * 2 + 1] = __floats2half2_rn(vv[j].z * SCALE, vv[j].w * SCALE);
        }
    }
}

// ------------------------------------------------------------------
// Kernel 2: TMA-fed fp16 mma.sync GEMM, mbarrier-only mainloop.
//   CTA (0,0) computes the global scalars after its TMA prologue
//   (reduce scratch lives in dynamic smem to keep TMA 128B alignment).
// ------------------------------------------------------------------
__device__ __forceinline__ float row_scale(int r, float sc) {
    float n = fmaxf(sqrtf(g_xn2[r]), EPSF);
    float z = sc * n;
    return atanhf(clip_artanh_arg(z)) / z;
}

__device__ __forceinline__ float blockReduceSumD(float v, float* sbuf) {
    #pragma unroll
    for (int o = 16; o > 0; o >>= 1) v += __shfl_xor_sync(0xffffffffu, v, o);
    int w = threadIdx.x >> 5;
    if ((threadIdx.x & 31) == 0) sbuf[w] = v;
    __syncthreads();
    if (threadIdx.x < 32) {
        float t = (threadIdx.x < 8) ? sbuf[threadIdx.x] : 0.f;
        #pragma unroll
        for (int o = 4; o > 0; o >>= 1) t += __shfl_xor_sync(0xffffffffu, t, o);
        if (threadIdx.x == 0) sbuf[0] = t;
    }
    __syncthreads();
    float r = sbuf[0];
    __syncthreads();
    return r;
}

__global__ void __launch_bounds__(256, 1) k_gemm(
    const __grid_constant__ CUtensorMap xmap,
    const __grid_constant__ CUtensorMap wmap,
    const float* __restrict__ bias,
    const float* __restrict__ anchors,
    const float* __restrict__ aw)
{
    extern __shared__ char smem[];
    uint32_t sb = smem_u32(smem);
    const int tid  = threadIdx.x;
    const int lane = tid & 31;
    const int warp = tid >> 5;
    const int bm = blockIdx.y * MT;
    const int bn = blockIdx.x * NT;
    const int wm = (warp >> 2) * 64;   // 2 M-warps
    const int wn = (warp & 3) * 64;    // 4 N-warps
    const uint32_t mbF = sb + SOFF_FULL;
    const uint32_t mbE = sb + SOFF_EMPTY;

    float acc[4][8][4];
    #pragma unroll
    for (int mi = 0; mi < 4; mi++)
        #pragma unroll
        for (int ni = 0; ni < 8; ni++)
            #pragma unroll
            for (int q = 0; q < 4; q++) acc[mi][ni][q] = 0.f;

    const int g  = lane >> 2;
    const int tg = lane & 3;

    // ldmatrix per-lane addressing (SW128 swizzle: row*128 + (kb ^ ((row&7)<<4)))
    const uint32_t a_row = wm + (lane & 15);
    const uint32_t aq    = ((lane >> 4) * 16) ^ ((a_row & 7) << 4);
    const uint32_t b_row = wn + ((lane >> 4) << 3) + (lane & 7);
    const uint32_t bq    = (((lane >> 3) & 1) * 16) ^ ((b_row & 7) << 4);

    if (tid == 0) {
        #pragma unroll
        for (int s = 0; s < NSTAGE; s++) {
            mbar_init(mbF + 8 * s, 1);
            mbar_init(mbE + 8 * s, 8);   // one arrive per warp
        }
    }
    __syncthreads();
    if (tid == 0) {
        #pragma unroll
        for (int s = 0; s < 3; s++) {
            uint32_t abase = sb + s * STAGE_BYTES;
            mbar_expect(mbF + 8 * s, STAGE_BYTES);
            tma2d(abase, &xmap, s * KC, bm, mbF + 8 * s);
            tma2d(abase + A_STAGE_BYTES, &wmap, s * KC, bn, mbF + 8 * s);
        }
    }

    // CTA (0,0): compute global scalars while other CTAs run their mainloop.
    if (blockIdx.x == 0 && blockIdx.y == 0) {
        float* sbuf = (float*)(smem + SOFF_SCRATCH);   // dynamic smem scratch
        float s = 0.f;
        for (int i = tid; i < NROWS; i += 256) s += g_sp[i];
        s = blockReduceSumD(s, sbuf);
        float c = s / (float)NROWS;

        for (int k = 0; k < NK; k++) {
            float v = 0.f;
            for (int j = tid; j < DIM; j += 256) {
                float a = anchors[k * DIM + j];
                v += a * a;
            }
            v = blockReduceSumD(v, sbuf);
            if (tid == 0) g_an2[k] = v;
        }
        if (tid == 0) {
            g_c = c;
            g_sc = sqrtf(c);
            float m = fmaxf(fmaxf(aw[0], aw[1]), fmaxf(aw[2], aw[3]));
            float e0 = expf(aw[0] - m), e1 = expf(aw[1] - m);
            float e2 = expf(aw[2] - m), e3 = expf(aw[3] - m);
            float inv = 1.f / (e0 + e1 + e2 + e3);
            g_w[0] = e0 * inv; g_w[1] = e1 * inv;
            g_w[2] = e2 * inv; g_w[3] = e3 * inv;
            __threadfence();
            atomicExch(&g_sflag, 1u);
        }
    }

    for (int i = 0; i < NITER; i++) {
        int s = i & 3;
        mbar_wait(mbF + 8 * s, (i >> 2) & 1);
        uint32_t abase = sb + s * STAGE_BYTES;
        uint32_t bbase = abase + A_STAGE_BYTES;

        #pragma unroll
        for (int ks = 0; ks < 4; ks++) {
            uint32_t a[4][4];
            #pragma unroll
            for (int mi = 0; mi < 4; mi++)
                ldsm4(abase + (a_row + mi * 16) * 128 + ((ks * 32) ^ aq),
                      a[mi][0], a[mi][1], a[mi][2], a[mi][3]);
            uint32_t b[8][2];
            #pragma unroll
            for (int p = 0; p < 4; p++)
                ldsm4(bbase + (b_row + p * 16) * 128 + ((ks * 32) ^ bq),
                      b[2 * p][0], b[2 * p][1], b[2 * p + 1][0], b[2 * p + 1][1]);
            #pragma unroll
            for (int mi = 0; mi < 4; mi++)
                #pragma unroll
                for (int ni = 0; ni < 8; ni++) {
                    asm volatile(
                        "mma.sync.aligned.m16n8k16.row.col.f32.f16.f16.f32 "
                        "{%0,%1,%2,%3}, {%4,%5,%6,%7}, {%8,%9}, {%0,%1,%2,%3};\n"
                        : "+f"(acc[mi][ni][0]), "+f"(acc[mi][ni][1]),
                          "+f"(acc[mi][ni][2]), "+f"(acc[mi][ni][3])
                        : "r"(a[mi][0]), "r"(a[mi][1]), "r"(a[mi][2]), "r"(a[mi][3]),
                          "r"(b[ni][0]), "r"(b[ni][1]));
                }
        }
        // Fragments for stage s fully consumed by this warp -> release buffer.
        if (lane == 0) mbar_arrive(mbE + 8 * s);

        // Producer: refill stage (i+3)&3 once all warps released it (iter i-1).
        if (tid == 0 && i + 3 < NITER) {
            int j = i + 3, s2 = j & 3, f = j >> 2;
            if (f >= 1) mbar_wait(mbE + 8 * s2, (f - 1) & 1);
            uint32_t ab2 = sb + s2 * STAGE_BYTES;
            mbar_expect(mbF + 8 * s2, STAGE_BYTES);
            tma2d(ab2, &xmap, j * KC, bm, mbF + 8 * s2);
            tma2d(ab2 + A_STAGE_BYTES, &wmap, j * KC, bn, mbF + 8 * s2);
        }
    }

    // Gate on scalars (CTA0 publishes long before wave-1 epilogues).
    if (tid == 0) {
        while (atomicAdd(&g_sflag, 0u) == 0u) __nanosleep(64);
    }
    __syncthreads();
    __threadfence();

    // Epilogue: h = s_row * acc/1024 + bias; fp16 store + per-row partials
    float sc = g_sc;
    float bz0[8], bz1[8];
    #pragma unroll
    for (int ni = 0; ni < 8; ni++) {
        int cc = bn + wn + ni * 8 + tg * 2;
        bz0[ni] = bias[cc];
        bz1[ni] = bias[cc + 1];
    }
    #pragma unroll
    for (int mi = 0; mi < 4; mi++) {
        int r0 = bm + wm + mi * 16 + g;
        float s0 = row_scale(r0, sc) * SCALE_INV;
        float s1 = row_scale(r0 + 8, sc) * SCALE_INV;
        float p0[5] = {0.f, 0.f, 0.f, 0.f, 0.f};
        float p1[5] = {0.f, 0.f, 0.f, 0.f, 0.f};
        #pragma unroll
        for (int ni = 0; ni < 8; ni++) {
            int cc = bn + wn + ni * 8 + tg * 2;
            float h00 = fmaf(s0, acc[mi][ni][0], bz0[ni]);
            float h01 = fmaf(s0, acc[mi][ni][1], bz1[ni]);
            float h10 = fmaf(s1, acc[mi][ni][2], bz0[ni]);
            float h11 = fmaf(s1, acc[mi][ni][3], bz1[ni]);
            *(__half2*)(g_hh + (size_t)r0 * DIM + cc) = __floats2half2_rn(h00, h01);
            *(__half2*)(g_hh + (size_t)(r0 + 8) * DIM + cc) = __floats2half2_rn(h10, h11);
            p0[0] += h00 * h00 + h01 * h01;
            p1[0] += h10 * h10 + h11 * h11;
            #pragma unroll
            for (int k = 0; k < NK; k++) {
                float a0 = anchors[k * DIM + cc];
                float a1 = anchors[k * DIM + cc + 1];
                p0[1 + k] += h00 * a0 + h01 * a1;
                p1[1 + k] += h10 * a0 + h11 * a1;
            }
        }
        #pragma unroll
        for (int q = 0; q < 5; q++) {
            p0[q] += __shfl_xor_sync(0xffffffffu, p0[q], 1);
            p0[q] += __shfl_xor_sync(0xffffffffu, p0[q], 2);
            p1[q] += __shfl_xor_sync(0xffffffffu, p1[q], 1);
            p1[q] += __shfl_xor_sync(0xffffffffu, p1[q], 2);
        }
        if (tg == 0) {
            int pi = blockIdx.x * 4 + (warp & 3);   // 8 n-blocks * 4 n-warps = 32
            float* d0 = g_part + ((size_t)r0 * NPART + pi) * 5;
            float* d1 = g_part + ((size_t)(r0 + 8) * NPART + pi) * 5;
            #pragma unroll
            for (int q = 0; q < 5; q++) { d0[q] = p0[q]; d1[q] = p1[q]; }
        }
    }
}

// ------------------------------------------------------------------
// Kernel 3: per-row coefficients + streaming combine (h from fp16)
// ------------------------------------------------------------------
__global__ __launch_bounds__(256) void k_final(const float* __restrict__ anchors,
                                               const float* __restrict__ tv,
                                               float* __restrict__ out) {
    int row = blockIdx.x;
    int tid = threadIdx.x;
    int w = tid >> 5, lane = tid & 31;

    // Reset the scalars flag for the next graph replay (stream-ordered
    // before the next k_gemm launch).
    if (row == 0 && tid == 0) g_sflag = 0u;

    __shared__ float sred[5];
    __shared__ float scoef[5];

    // Reduce 32 partials x 5 quantities: warp q handles quantity q
    if (w < 5) {
        const float* pp = g_part + (size_t)row * NPART * 5;
        float v = pp[lane * 5 + w];
        #pragma unroll
        for (int o = 16; o > 0; o >>= 1) v += __shfl_xor_sync(0xffffffffu, v, o);
        if (lane == 0) sred[w] = v;
    }
    __syncthreads();

    if (tid == 0) {
        float c = g_c, sc = g_sc;
        float h2 = sred[0];
        float m = fmaxf(sqrtf(h2), EPSF);
        float scm = sc * m;
        float e = tanhf(scm) / scm;
        float y2 = e * e * h2;
        float Acoef = 0.f;
        #pragma unroll
        for (int k = 0; k < NK; k++) {
            float ya  = e * sred[1 + k];
            float an2 = g_an2[k];
            float P  = 1.f - 2.f * c * ya + c * an2;
            float Q  = 1.f - c * y2;
            float D1 = fmaxf(1.f - 2.f * c * ya + c * c * y2 * an2, EPSF);
            float diff2 = (P * P * y2 - 2.f * P * Q * ya + Q * Q * an2) / (D1 * D1);
            float nd = fmaxf(sqrtf(fmaxf(diff2, 0.f)), EPSF);
            float z  = sc * nd;
            float ar = atanhf(clip_artanh_arg(z));
            float tau = tanhf(tv[k] * ar) / z;
            float uy = -tau * P / D1;
            float ua =  tau * Q / D1;
            float xys = uy * y2 + ua * ya;
            float y2s = tau * tau * diff2;
            float den2 = fmaxf(1.f + 2.f * c * xys + c * c * y2 * y2s, EPSF);
            float alpha = (1.f + 2.f * c * xys + c * y2s + (1.f - c * y2) * uy) / den2;
            float beta  = (1.f - c * y2) * ua / den2;
            float w2 = g_w[k];
            Acoef += w2 * alpha;
            scoef[1 + k] = w2 * beta;
        }
        scoef[0] = Acoef * e;
    }
    __syncthreads();

    float Ae = scoef[0];
    float B0 = scoef[1], B1 = scoef[2], B2 = scoef[3], B3 = scoef[4];
    const __half2* hr = (const __half2*)(g_hh + (size_t)row * DIM);
    const float4* a0 = (const float4*)(anchors);
    const float4* a1 = (const float4*)(anchors + DIM);
    const float4* a2 = (const float4*)(anchors + 2 * DIM);
    const float4* a3 = (const float4*)(anchors + 3 * DIM);
    float4* outr = (float4*)(out + (size_t)row * DIM);
    #pragma unroll
    for (int i = 0; i < 2; i++) {
        int idx = tid + i * 256;
        float2 hlo = __half22float2(hr[idx * 2]);
        float2 hhi = __half22float2(hr[idx * 2 + 1]);
        float4 v0 = a0[idx], v1 = a1[idx], v2 = a2[idx], v3 = a3[idx];
        float4 o;
        o.x = Ae * hlo.x; o.y = Ae * hlo.y; o.z = Ae * hhi.x; o.w = Ae * hhi.y;
        o.x = fmaf(B0, v0.x, o.x); o.y = fmaf(B0, v0.y, o.y);
        o.z = fmaf(B0, v0.z, o.z); o.w = fmaf(B0, v0.w, o.w);
        o.x = fmaf(B1, v1.x, o.x); o.y = fmaf(B1, v1.y, o.y);
        o.z = fmaf(B1, v1.z, o.z); o.w = fmaf(B1, v1.w, o.w);
        o.x = fmaf(B2, v2.x, o.x); o.y = fmaf(B2, v2.y, o.y);
        o.z = fmaf(B2, v2.z, o.z); o.w = fmaf(B2, v2.w, o.w);
        o.x = fmaf(B3, v3.x, o.x); o.y = fmaf(B3, v3.y, o.y);
        o.z = fmaf(B3, v3.z, o.z); o.w = fmaf(B3, v3.w, o.w);
        outr[idx] = o;
    }
}

// ------------------------------------------------------------------
// Launch
// ------------------------------------------------------------------
typedef CUresult (*tmapEncodeFn)(
    CUtensorMap*, CUtensorMapDataType, cuuint32_t, void*,
    const cuuint64_t*, const cuuint64_t*, const cuuint32_t*, const cuuint32_t*,
    CUtensorMapInterleave, CUtensorMapSwizzle, CUtensorMapL2promotion,
    CUtensorMapFloatOOBfill);

extern "C" void kernel_launch(void* const* d_in, const int* in_sizes, int n_in,
                              void* d_out, int out_size) {
    const float* x       = (const float*)d_in[0];
    const float* weight  = (const float*)d_in[1];
    const float* bias    = (const float*)d_in[2];
    const float* cw      = (const float*)d_in[3];
    const float* cb      = (const float*)d_in[4];
    const float* anchors = (const float*)d_in[5];
    const float* tv      = (const float*)d_in[6];
    const float* aw      = (const float*)d_in[7];
    float* out = (float*)d_out;

    cudaFuncSetAttribute(k_gemm, cudaFuncAttributeMaxDynamicSharedMemorySize,
                         SMEM_TOTAL);

    // Build tensor maps for the fp16 scratch tensors
    void* xptr = nullptr;
    void* wptr = nullptr;
    cudaGetSymbolAddress(&xptr, g_xh);
    cudaGetSymbolAddress(&wptr, g_wh);

    tmapEncodeFn encode = nullptr;
    cudaDriverEntryPointQueryResult qr;
    cudaGetDriverEntryPointByVersion("cuTensorMapEncodeTiled", (void**)&encode,
                                     12000, cudaEnableDefault, &qr);

    CUtensorMap xmap, wmap;
    {
        cuuint64_t gdim[2] = {DIM, NROWS};
        cuuint64_t gstr[1] = {DIM * 2};           // bytes between rows
        cuuint32_t box[2]  = {KC, MT};            // 64 halves x 128 rows
        cuuint32_t est[2]  = {1, 1};
        encode(&xmap, CU_TENSOR_MAP_DATA_TYPE_UINT16, 2, xptr,
               gdim, gstr, box, est,
               CU_TENSOR_MAP_INTERLEAVE_NONE, CU_TENSOR_MAP_SWIZZLE_128B,
               CU_TENSOR_MAP_L2_PROMOTION_L2_128B,
               CU_TENSOR_MAP_FLOAT_OOB_FILL_NONE);
    }
    {
        cuuint64_t gdim[2] = {DIM, DIM};
        cuuint64_t gstr[1] = {DIM * 2};
        cuuint32_t box[2]  = {KC, NT};            // 64 halves x 256 rows
        cuuint32_t est[2]  = {1, 1};
        encode(&wmap, CU_TENSOR_MAP_DATA_TYPE_UINT16, 2, wptr,
               gdim, gstr, box, est,
               CU_TENSOR_MAP_INTERLEAVE_NONE, CU_TENSOR_MAP_SWIZZLE_128B,
               CU_TENSOR_MAP_L2_PROMOTION_L2_128B,
               CU_TENSOR_MAP_FLOAT_OOB_FILL_NONE);
    }

    k_prep<<<PREP_TOTAL, 256>>>(x, cw, cb, weight);
    dim3 grid(DIM / NT, NROWS / MT);       // 8 x 32 = 256 CTAs
    k_gemm<<<grid, 256, SMEM_TOTAL>>>(xmap, wmap, bias, anchors, aw);
    k_final<<<NROWS, 256>>>(anchors, tv, out);
}